// round 4
// baseline (speedup 1.0000x reference)
#include <cuda_runtime.h>
#include <math.h>

// CausalSTFT: out[b,k,t] = |sum_n win[n]*x[b, t*HOP-1023+n] * e^{-2pi i k n/1024}|
// Implemented as: Hann window (taken from weight row 0, which is exactly the
// window since cos(0*n)=1) -> pack even/odd -> 512-pt complex radix-2 DIF FFT
// in shared memory -> real-FFT recombination -> magnitude with eps clip.
//
// Block = 8 consecutive frames of one batch row. 512 threads.
//   - input tile loaded once (frames overlap by 768 samples)
//   - output writes coalesced along t (8 consecutive t = one 32B sector)

#define HOPK     256
#define NFFT     1024
#define NHALF    512
#define FPB      8          // frames per block
#define NT       512        // threads per block
#define TFR      2048       // frames per batch row
#define KB       513        // output bins
#define TILE_IN  2816       // 1023 + 7*256 + 1 + ... = span of 8 overlapping frames
#define ZSTRIDE  513        // padded frame stride in s_z (bank-conflict avoidance)

__global__ __launch_bounds__(NT) void causal_stft_kernel(
    const float* __restrict__ x,
    const float* __restrict__ weight,   // row 0 (first 1024 floats) == Hann window
    float* __restrict__ out)
{
    __shared__ float2 s_z[FPB * ZSTRIDE];   // 32832 B
    __shared__ float2 s_tw[256];            //  2048 B  (e^{-2pi i j/512})
    __shared__ float2 s_in2[TILE_IN / 2];   // 11264 B  (float2 for alignment)
    float* s_in = (float*)s_in2;

    const int tid = threadIdx.x;
    const int b   = blockIdx.y;
    const int t0  = blockIdx.x * FPB;
    const float* xb = x + (size_t)b * (size_t)(HOPK * TFR);
    const int g0 = t0 * HOPK - (NFFT - 1);

    // --- FFT twiddle table: e^{-2pi i j / 512} = (cos, sin) of pi*(-j/256) ---
    for (int j = tid; j < 256; j += NT) {
        float s, c;
        sincospif(-(float)j * (1.0f / 256.0f), &s, &c);
        s_tw[j] = make_float2(c, s);
    }
    // --- stage input tile (zero-pad left edge) ---
    for (int u = tid; u < TILE_IN; u += NT) {
        int g = g0 + u;
        s_in[u] = (g >= 0) ? __ldg(xb + g) : 0.0f;
    }
    __syncthreads();

    // --- window + pack even/odd into complex:  z[m] = xw[2m] + i*xw[2m+1] ---
    #pragma unroll
    for (int i = 0; i < 8; ++i) {
        int idx = tid + i * NT;           // 0..4095
        int m = idx & (NHALF - 1);
        int f = idx >> 9;
        float a  = s_in[f * HOPK + 2 * m];
        float c  = s_in[f * HOPK + 2 * m + 1];
        float w0 = __ldg(weight + 2 * m);       // Hann window, exact
        float w1 = __ldg(weight + 2 * m + 1);
        s_z[f * ZSTRIDE + m] = make_float2(a * w0, c * w1);
    }
    __syncthreads();

    // --- 512-pt radix-2 DIF FFT, 64 threads per frame, natural -> bit-rev ---
    {
        const int f = tid >> 6;
        const int l = tid & 63;
        float2* zf = s_z + f * ZSTRIDE;
        #pragma unroll
        for (int s = 0; s < 9; ++s) {
            const int hs = 8 - s;
            const int h  = 1 << hs;
            #pragma unroll
            for (int i = 0; i < 4; ++i) {
                int j  = l + 64 * i;                       // butterfly id 0..255
                int p  = j & (h - 1);
                int i0 = ((j >> hs) << (hs + 1)) | p;
                float2 a = zf[i0];
                float2 c = zf[i0 + h];
                float2 w = s_tw[p << s];
                float dr = a.x - c.x, di = a.y - c.y;
                zf[i0]     = make_float2(a.x + c.x, a.y + c.y);
                zf[i0 + h] = make_float2(dr * w.x - di * w.y,
                                         dr * w.y + di * w.x);
            }
            __syncthreads();
        }
    }

    // --- real-FFT recombination + magnitude, coalesced along t ---
    // Z[k] sits at bit-reversed index. X[k] = E[k] + e^{-2pi i k/1024} O[k]
    #pragma unroll
    for (int i = 0; i < 9; ++i) {
        int idx = tid + i * NT;
        if (idx < KB * FPB) {
            int f  = idx & 7;
            int k  = idx >> 3;
            int kk = k & (NHALF - 1);
            int km = (NHALF - k) & (NHALF - 1);
            int rk = (int)(__brev((unsigned)kk) >> 23);
            int rm = (int)(__brev((unsigned)km) >> 23);
            float2 Zk = s_z[f * ZSTRIDE + rk];
            float2 Zm = s_z[f * ZSTRIDE + rm];
            float Er = 0.5f * (Zk.x + Zm.x);
            float Ei = 0.5f * (Zk.y - Zm.y);
            float Or = 0.5f * (Zk.y + Zm.y);
            float Oi = 0.5f * (Zm.x - Zk.x);
            float sn, cs;
            sincospif(-(float)k * (1.0f / 512.0f), &sn, &cs);  // e^{-2pi i k/1024}
            float Xr = Er + cs * Or - sn * Oi;
            float Xi = Ei + cs * Oi + sn * Or;
            float p2 = Xr * Xr + Xi * Xi;
            out[((size_t)b * KB + k) * TFR + (t0 + f)] = sqrtf(fmaxf(p2, 1e-12f));
        }
    }
}

extern "C" void kernel_launch(void* const* d_in, const int* in_sizes, int n_in,
                              void* d_out, int out_size)
{
    const float* x = (const float*)d_in[0];
    const float* w = (const float*)d_in[1];
    int xs = in_sizes[0];
    if (n_in >= 2 && in_sizes[0] < in_sizes[1]) {   // x is the larger tensor
        const float* t = x; x = w; w = t;
        xs = in_sizes[1];
    }
    int B = xs / (HOPK * TFR);                      // 16
    dim3 grid(TFR / FPB, B);
    causal_stft_kernel<<<grid, NT>>>(x, w, (float*)d_out);
}